// round 13
// baseline (speedup 1.0000x reference)
#include <cuda_runtime.h>
#include <cuda_fp16.h>
#include <cstdint>

#define NR 8192
#define DD 256

// ---------------- device scratch (allocation-free) ----------------
__device__ __align__(256) __half g_Xhi[NR * DD], g_Xlo[NR * DD];
__device__ __align__(256) __half g_XThi[DD * NR];
__device__ __align__(256) __half g_Whi[512 * DD], g_Wlo[512 * DD];     // [Rt/16 ; Et]
__device__ __align__(256) __half g_QKhi[NR * 512], g_QKlo[NR * 512];   // Q cols 0-255, K cols 256-511
__device__ __align__(256) float  g_L[(size_t)NR * NR];
__device__ __align__(256) float  g_rowM[NR], g_rowInv[NR];
__device__ __align__(256) float  g_Opart[2 * NR * DD];                 // split-K partials (16 MB)

// ---------------- PTX helpers ----------------
__device__ __forceinline__ uint32_t s2u(const void* p) {
    uint32_t a;
    asm("{ .reg .u64 t; cvta.to.shared.u64 t, %1; cvt.u32.u64 %0, t; }" : "=r"(a) : "l"(p));
    return a;
}
__device__ __forceinline__ void cpasync16(uint32_t dst, const void* src) {
    asm volatile("cp.async.cg.shared.global [%0], [%1], 16;" :: "r"(dst), "l"(src));
}
__device__ __forceinline__ void cp_commit() {
    asm volatile("cp.async.commit_group;" ::: "memory");
}
template <int N>
__device__ __forceinline__ void cp_wait() {
    asm volatile("cp.async.wait_group %0;" :: "n"(N) : "memory");
}
__device__ __forceinline__ void ldsm4(uint32_t* r, uint32_t a) {
    asm volatile("ldmatrix.sync.aligned.m8n8.x4.shared.b16 {%0,%1,%2,%3}, [%4];"
                 : "=r"(r[0]), "=r"(r[1]), "=r"(r[2]), "=r"(r[3]) : "r"(a));
}
__device__ __forceinline__ void mma16816(float* d, const uint32_t* a, const uint32_t* b) {
    asm volatile(
        "mma.sync.aligned.m16n8k16.row.col.f32.f16.f16.f32 "
        "{%0,%1,%2,%3}, {%4,%5,%6,%7}, {%8,%9}, {%0,%1,%2,%3};"
        : "+f"(d[0]), "+f"(d[1]), "+f"(d[2]), "+f"(d[3])
        : "r"(a[0]), "r"(a[1]), "r"(a[2]), "r"(a[3]), "r"(b[0]), "r"(b[1]));
}

// ---------------- prep: fp16 hi/lo splits ----------------
__global__ void __launch_bounds__(256) prep_params(const float* __restrict__ R,
                                                   const float* __restrict__ E) {
    int idx = blockIdx.x * 256 + threadIdx.x;   // 65536
    int k = idx >> 8, j = idx & 255;            // R[k][j]
    float r = R[idx] * 0.0625f;                 // fold 1/sqrt(d)=1/16 into rotation
    __half h = __float2half_rn(r);
    g_Whi[j * DD + k] = h;
    g_Wlo[j * DD + k] = __float2half_rn(r - __half2float(h));
    float e = E[idx];
    h = __float2half_rn(e);
    g_Whi[(256 + j) * DD + k] = h;
    g_Wlo[(256 + j) * DD + k] = __float2half_rn(e - __half2float(h));
}

__global__ void __launch_bounds__(256) prep_x(const float* __restrict__ X) {
    int idx = blockIdx.x * 256 + threadIdx.x;   // 2M
    int r = idx >> 8, c = idx & 255;
    float v = X[idx];
    __half h = __float2half_rn(v);
    g_Xhi[idx] = h;
    g_Xlo[idx] = __float2half_rn(v - __half2float(h));
    g_XThi[(size_t)c * NR + r] = h;
}

// =====================================================================
// Persistent wide 3-product GEMM: C = A @ B^T, CTA tile 128x256,
// 256 threads = 8 warps as 2m x 4n, each warp 64x64. BK=64,
// continuous 2-stage ring. (R9 interleaved MMA schedule.)
// mode 0: split fp16 out (Chi/Clo). mode 1: fp32 out (Cf).
// =====================================================================
#define STG512 98304

__device__ __forceinline__ void load512(char* st,
    const __half* pAh, const __half* pAl, int lda,
    const __half* pBh, const __half* pBl, int ldb, int kc, int tid) {
    const uint32_t b0 = s2u(st);
    #pragma unroll
    for (int i = 0; i < 4; ++i) {             // A tiles: 128x64
        int id = tid + i * 256;
        int r = id >> 3, q = id & 7;
        uint32_t off = (uint32_t)(r * 128) + (uint32_t)((q ^ (r & 7)) << 4);
        const size_t g = (size_t)r * lda + kc + q * 8;
        cpasync16(b0 + off, pAh + g);
        cpasync16(b0 + 16384 + off, pAl + g);
    }
    #pragma unroll
    for (int i = 0; i < 8; ++i) {             // B tiles: 256x64
        int id = tid + i * 256;
        int r = id >> 3, q = id & 7;
        uint32_t off = (uint32_t)(r * 128) + (uint32_t)((q ^ (r & 7)) << 4);
        const size_t g = (size_t)r * ldb + kc + q * 8;
        cpasync16(b0 + 32768 + off, pBh + g);
        cpasync16(b0 + 65536 + off, pBl + g);
    }
}

__device__ __forceinline__ void compute512(char* st, float acc[4][8][4],
                                           int lane, int wm, int wn) {
    const uint32_t bA = s2u(st), bAl = bA + 16384, bB = bA + 32768, bBl = bA + 65536;
    #pragma unroll
    for (int k16 = 0; k16 < 4; ++k16) {
        uint32_t ah[4][4], al[4][4];
        #pragma unroll
        for (int mt = 0; mt < 4; ++mt) {
            int row = wm * 64 + mt * 16 + (lane & 15);
            int c = k16 * 2 + (lane >> 4);
            uint32_t off = (uint32_t)(row * 128) + (uint32_t)((c ^ (row & 7)) << 4);
            ldsm4(ah[mt], bA + off);
            ldsm4(al[mt], bAl + off);
        }
        #pragma unroll
        for (int p = 0; p < 4; ++p) {
            int n = wn * 64 + p * 16 + ((lane >> 4) << 3) + (lane & 7);
            int c = k16 * 2 + ((lane >> 3) & 1);
            uint32_t off = (uint32_t)(n * 128) + (uint32_t)((c ^ (n & 7)) << 4);
            uint32_t bh[4], bl[4];
            ldsm4(bh, bB + off);
            ldsm4(bl, bBl + off);
            #pragma unroll
            for (int mt = 0; mt < 4; ++mt) {
                mma16816(acc[mt][2 * p + 0], ah[mt], &bh[0]);
                mma16816(acc[mt][2 * p + 1], ah[mt], &bh[2]);
                mma16816(acc[mt][2 * p + 0], al[mt], &bh[0]);
                mma16816(acc[mt][2 * p + 1], al[mt], &bh[2]);
                mma16816(acc[mt][2 * p + 0], ah[mt], &bl[0]);
                mma16816(acc[mt][2 * p + 1], ah[mt], &bl[2]);
            }
        }
    }
}

__device__ __forceinline__ void tile_ptrs512(int t, int bxm, int bxs,
    const __half* Ahi, const __half* Alo, const __half* Bhi, const __half* Blo,
    int lda, int ldb,
    const __half*& pAh, const __half*& pAl, const __half*& pBh, const __half*& pBl) {
    int by = t >> bxs, bx = t & bxm;
    pAh = Ahi + (size_t)(by * 128) * lda;
    pAl = Alo + (size_t)(by * 128) * lda;
    pBh = Bhi + (size_t)(bx * 256) * ldb;
    pBl = Blo + (size_t)(bx * 256) * ldb;
}

__global__ void __launch_bounds__(256, 1) gemm512p(
    const __half* __restrict__ Ahi, const __half* __restrict__ Alo, int lda,
    const __half* __restrict__ Bhi, const __half* __restrict__ Blo, int ldb,
    int K, int NT, int bxm, int bxs, int mode, float* __restrict__ Cf,
    __half* __restrict__ Chi, __half* __restrict__ Clo, int ldc) {
    extern __shared__ char sm[];
    const int tid = threadIdx.x, lane = tid & 31, wid = tid >> 5;
    const int wm = wid >> 2, wn = wid & 3;
    const int NC = K >> 6;

    int lt = blockIdx.x, lc = 0, ldbuf = 0;
    const __half *lAh, *lAl, *lBh, *lBl;
    tile_ptrs512(lt, bxm, bxs, Ahi, Alo, Bhi, Blo, lda, ldb, lAh, lAl, lBh, lBl);

    #pragma unroll
    for (int i = 0; i < 2; ++i) {
        if (lt < NT) {
            load512(sm + ldbuf * STG512, lAh, lAl, lda, lBh, lBl, ldb, lc * 64, tid);
            ldbuf ^= 1;
            if (++lc == NC) {
                lc = 0; lt += gridDim.x;
                if (lt < NT) tile_ptrs512(lt, bxm, bxs, Ahi, Alo, Bhi, Blo, lda, ldb, lAh, lAl, lBh, lBl);
            }
        }
        cp_commit();
    }

    int cbuf = 0;
    for (int t = blockIdx.x; t < NT; t += gridDim.x) {
        float acc[4][8][4];
        #pragma unroll
        for (int a = 0; a < 4; ++a)
            #pragma unroll
            for (int b = 0; b < 8; ++b)
                #pragma unroll
                for (int c = 0; c < 4; ++c) acc[a][b][c] = 0.f;

        for (int c = 0; c < NC; ++c) {
            cp_wait<1>();
            __syncthreads();
            compute512(sm + cbuf * STG512, acc, lane, wm, wn);
            cbuf ^= 1;
            __syncthreads();
            if (lt < NT) {
                load512(sm + ldbuf * STG512, lAh, lAl, lda, lBh, lBl, ldb, lc * 64, tid);
                ldbuf ^= 1;
                if (++lc == NC) {
                    lc = 0; lt += gridDim.x;
                    if (lt < NT) tile_ptrs512(lt, bxm, bxs, Ahi, Alo, Bhi, Blo, lda, ldb, lAh, lAl, lBh, lBl);
                }
            }
            cp_commit();
        }

        const int rowT = (t >> bxs) * 128, colT = (t & bxm) * 256;
        const int quad = lane >> 2, tc = lane & 3;
        #pragma unroll
        for (int mt = 0; mt < 4; ++mt) {
            #pragma unroll
            for (int h = 0; h < 2; ++h) {
                const int row = rowT + wm * 64 + mt * 16 + quad + h * 8;
                #pragma unroll
                for (int nt = 0; nt < 8; ++nt) {
                    const int col = colT + wn * 64 + nt * 8 + tc * 2;
                    float v0 = acc[mt][nt][h * 2 + 0];
                    float v1 = acc[mt][nt][h * 2 + 1];
                    if (mode == 1) {
                        *(float2*)(Cf + (size_t)row * ldc + col) = make_float2(v0, v1);
                    } else {
                        __half h0 = __float2half_rn(v0), h1 = __float2half_rn(v1);
                        __half l0 = __float2half_rn(v0 - __half2float(h0));
                        __half l1 = __float2half_rn(v1 - __half2float(h1));
                        *(__half2*)(Chi + (size_t)row * ldc + col) = __halves2half2(h0, h1);
                        *(__half2*)(Clo + (size_t)row * ldc + col) = __halves2half2(l0, l1);
                    }
                }
            }
        }
    }
}

// ---------------- row stats: m = max(L_row), inv = 1/sum(exp(L-m)) ----------------
__global__ void __launch_bounds__(256) softstats_k() {
    __shared__ float warpred[8];
    __shared__ float bc;
    const int row = blockIdx.x;
    const int t = threadIdx.x, lane = t & 31, w = t >> 5;
    const float4* Lr = (const float4*)(g_L + (size_t)row * NR);
    float4 v[8];
    float m = -3.4e38f;
    #pragma unroll
    for (int i = 0; i < 8; ++i) {
        v[i] = Lr[t + i * 256];
        m = fmaxf(m, fmaxf(fmaxf(v[i].x, v[i].y), fmaxf(v[i].z, v[i].w)));
    }
    #pragma unroll
    for (int o = 16; o > 0; o >>= 1) m = fmaxf(m, __shfl_xor_sync(0xFFFFFFFFu, m, o));
    if (lane == 0) warpred[w] = m;
    __syncthreads();
    if (w == 0) {
        float x = (lane < 8) ? warpred[lane] : -3.4e38f;
        #pragma unroll
        for (int o = 4; o > 0; o >>= 1) x = fmaxf(x, __shfl_xor_sync(0xFFFFFFFFu, x, o));
        if (lane == 0) bc = x;
    }
    __syncthreads();
    m = bc;
    float sum = 0.f;
    #pragma unroll
    for (int i = 0; i < 8; ++i) {
        sum += __expf(v[i].x - m) + __expf(v[i].y - m)
             + __expf(v[i].z - m) + __expf(v[i].w - m);
    }
    #pragma unroll
    for (int o = 16; o > 0; o >>= 1) sum += __shfl_xor_sync(0xFFFFFFFFu, sum, o);
    if (lane == 0) warpred[w] = sum;
    __syncthreads();
    if (w == 0) {
        float x = (lane < 8) ? warpred[lane] : 0.f;
        #pragma unroll
        for (int o = 4; o > 0; o >>= 1) x += __shfl_xor_sync(0xFFFFFFFFu, x, o);
        if (lane == 0) {
            g_rowM[row] = m;
            g_rowInv[row] = 1.0f / x;
        }
    }
}

// =====================================================================
// Fused O: Opart[half] = exp(L[:, half] - m)/Z @ X^T[half]
// Grid (2, 64): x = KV half, y = row tile. 512 threads = 16 warps 4m x 4n,
// warp tile 32x64. BK=64 over KV. L prefetched to regs, exp'd to fp16
// P tile in smem (ping-pong); X via 2-stage cp.async ring.
// smem: P 2x16KB @0, X 2x32KB @32768 -> 96 KB.
// =====================================================================
__global__ void __launch_bounds__(512, 1) gemm_po(float* __restrict__ Opart) {
    extern __shared__ char sm[];
    const int tid = threadIdx.x, lane = tid & 31, wid = tid >> 5;
    const int wm = wid >> 2, wn = wid & 3;
    const int half = blockIdx.x;
    const int rowA = blockIdx.y * 128;
    const int kvBase = half * (NR / 2);
    const int NCH = (NR / 2) >> 6;   // 64

    // per-thread L row assignment: 4 threads per row, 16 consecutive cols each
    const int rowL = tid >> 2;            // 0..127
    const int cb = (tid & 3) * 16;        // col base within 64-chunk
    const float rm = g_rowM[rowA + rowL];
    const float rinv = g_rowInv[rowA + rowL];
    const float4* Lp = (const float4*)(g_L + (size_t)(rowA + rowL) * NR + kvBase + cb);

    float acc[2][8][4];
    #pragma unroll
    for (int a = 0; a < 2; ++a)
        #pragma unroll
        for (int b = 0; b < 8; ++b)
            #pragma unroll
            for (int c = 0; c < 4; ++c) acc[a][b][c] = 0.f;

    // X loads: 256 rows x 64 cols fp16 per chunk = 2048 vec16 / 512 thr = 4 each
    auto load_x = [&](int buf, int kc) {
        const uint32_t bx = s2u(sm + 32768 + buf * 32768);
        #pragma unroll
        for (int i = 0; i < 4; ++i) {
            int id = tid + i * 512;
            int r = id >> 3, q = id & 7;
            uint32_t off = (uint32_t)(r * 128) + (uint32_t)((q ^ (r & 7)) << 4);
            cpasync16(bx + off, g_XThi + (size_t)r * NR + kvBase + kc + q * 8);
        }
    };

    // prologue
    float4 lv[4];
    #pragma unroll
    for (int i = 0; i < 4; ++i) lv[i] = Lp[i];
    load_x(0, 0);
    cp_commit();
    load_x(1, 64);
    cp_commit();

    for (int c = 0; c < NCH; ++c) {
        // convert lv -> P[c&1] (exp + scale + pack fp16, swizzled STS)
        {
            char* pb = sm + (c & 1) * 16384;
            __half hp[16];
            #pragma unroll
            for (int i = 0; i < 4; ++i) {
                hp[i * 4 + 0] = __float2half_rn(__expf(lv[i].x - rm) * rinv);
                hp[i * 4 + 1] = __float2half_rn(__expf(lv[i].y - rm) * rinv);
                hp[i * 4 + 2] = __float2half_rn(__expf(lv[i].z - rm) * rinv);
                hp[i * 4 + 3] = __float2half_rn(__expf(lv[i].w - rm) * rinv);
            }
            #pragma unroll
            for (int u = 0; u < 2; ++u) {
                int q = (tid & 3) * 2 + u;
                uint32_t off = (uint32_t)(rowL * 128) + (uint32_t)((q ^ (rowL & 7)) << 4);
                uint4 w;
                __half2 p0 = __halves2half2(hp[u * 8 + 0], hp[u * 8 + 1]);
                __half2 p1 = __halves2half2(hp[u * 8 + 2], hp[u * 8 + 3]);
                __half2 p2 = __halves2half2(hp[u * 8 + 4], hp[u * 8 + 5]);
                __half2 p3 = __halves2half2(hp[u * 8 + 6], hp[u * 8 + 7]);
                w.x = *(uint32_t*)&p0; w.y = *(uint32_t*)&p1;
                w.z = *(uint32_t*)&p2; w.w = *(uint32_t*)&p3;
                *(uint4*)(pb + off) = w;
            }
        }
        // prefetch next L chunk into regs (lands during MMA)
        if (c + 1 < NCH) {
            #pragma unroll
            for (int i = 0; i < 4; ++i) lv[i] = Lp[(c + 1) * 16 + i];
        }
        cp_wait<1>();
        __syncthreads();     // X(c) landed; P(c&1) visible to all warps
        {
            const uint32_t bP = s2u(sm + (c & 1) * 16384);
            const uint32_t bX = s2u(sm + 32768 + (c & 1) * 32768);
            #pragma unroll
            for (int k16 = 0; k16 < 4; ++k16) {
                uint32_t a[2][4];
                #pragma unroll
                for (int mt = 0; mt < 2; ++mt) {
                    int row = wm * 32 + mt * 16 + (lane & 15);
                    int q = k16 * 2 + (lane >> 4);
                    uint32_t off = (uint32_t)(row * 128) + (uint32_t)((q ^ (row & 7)) << 4);
                    ldsm4(a[mt], bP + off);
                }
                #pragma unroll
                for (int p = 0; p < 4; ++p) {
                    int n = wn * 64 + p * 16 + ((lane >> 4) << 3) + (lane & 7);
                    int q = k16 * 2 + ((lane >> 3) & 1);
                    uint32_t off = (uint32_t)(n * 128) + (uint32_t)((q ^ (n & 7)) << 4);
                    uint32_t bh[4];
                    ldsm4(bh, bX + off);
                    #pragma unroll
                    for (int mt = 0; mt < 2; ++mt) {
                        mma16816(acc[mt][2 * p + 0], a[mt], &bh[0]);
                        mma16816(acc[mt][2 * p + 1], a[mt], &bh[2]);
                    }
                }
            }
        }
        __syncthreads();     // all done with P(c&1)/X(c&1) before overwrite
        if (c + 2 < NCH) load_x(c & 1, (c + 2) * 64);
        cp_commit();
    }

    // epilogue: fp32 partials
    float* Co = Opart + (size_t)half * NR * DD;
    const int quad = lane >> 2, tc = lane & 3;
    #pragma unroll
    for (int mt = 0; mt < 2; ++mt)
        #pragma unroll
        for (int h = 0; h < 2; ++h) {
            const int row = rowA + wm * 32 + mt * 16 + quad + h * 8;
            #pragma unroll
            for (int nt = 0; nt < 8; ++nt) {
                const int col = wn * 64 + nt * 8 + tc * 2;
                *(float2*)(Co + (size_t)row * DD + col) =
                    make_float2(acc[mt][nt][h * 2 + 0], acc[mt][nt][h * 2 + 1]);
            }
        }
}

// ---------------- combine split-K partials ----------------
__global__ void __launch_bounds__(256) combine_o(float* __restrict__ out) {
    int i = blockIdx.x * 256 + threadIdx.x;   // float4 index; 524288 total
    const float4* p0 = (const float4*)g_Opart;
    const float4* p1 = (const float4*)(g_Opart + (size_t)NR * DD);
    float4 a = p0[i], b = p1[i];
    ((float4*)out)[i] = make_float4(a.x + b.x, a.y + b.y, a.z + b.z, a.w + b.w);
}

// ---------------- launch ----------------
extern "C" void kernel_launch(void* const* d_in, const int* in_sizes, int n_in,
                              void* d_out, int out_size) {
    const float* R = (const float*)d_in[0];
    const float* E = (const float*)d_in[1];
    const float* X = (const float*)d_in[2];
    float* out = (float*)d_out;

    const int SMEMW = 2 * STG512;        // 192 KB
    const int SMEMP = 98304;             // 96 KB
    cudaFuncSetAttribute(gemm512p, cudaFuncAttributeMaxDynamicSharedMemorySize, SMEMW);
    cudaFuncSetAttribute(gemm_po, cudaFuncAttributeMaxDynamicSharedMemorySize, SMEMP);

    void *xhi, *xlo, *whi, *wlo, *qkhi, *qklo, *lptr, *opart;
    cudaGetSymbolAddress(&xhi, g_Xhi);   cudaGetSymbolAddress(&xlo, g_Xlo);
    cudaGetSymbolAddress(&whi, g_Whi);   cudaGetSymbolAddress(&wlo, g_Wlo);
    cudaGetSymbolAddress(&qkhi, g_QKhi); cudaGetSymbolAddress(&qklo, g_QKlo);
    cudaGetSymbolAddress(&lptr, g_L);
    cudaGetSymbolAddress(&opart, g_Opart);

    prep_params<<<DD * DD / 256, 256>>>(R, E);
    prep_x<<<NR, 256>>>(X);

    // QK = X @ [R/16 | E]  (split out, ldc=512); 128 tiles (2 x 64)
    gemm512p<<<128, 256, SMEMW>>>((__half*)xhi, (__half*)xlo, DD,
                                  (__half*)whi, (__half*)wlo, DD,
                                  DD, 128, 1, 1, 0, nullptr,
                                  (__half*)qkhi, (__half*)qklo, 512);
    // L = Q @ K^T  (fp32 out); 2048 tiles (32 x 64), persistent 148 CTAs
    gemm512p<<<148, 256, SMEMW>>>((__half*)qkhi, (__half*)qklo, 512,
                                  (__half*)qkhi + 256, (__half*)qklo + 256, 512,
                                  DD, 2048, 31, 5, 1, (float*)lptr,
                                  nullptr, nullptr, NR);
    // row stats (m, 1/Z)
    softstats_k<<<NR, 256>>>();
    // fused exp + O partials: grid (kv half, row tile)
    gemm_po<<<dim3(2, 64), 512, SMEMP>>>((float*)opart);
    // combine partials -> out
    combine_o<<<(NR * DD / 4) / 256, 256>>>(out);
}

// round 14
// speedup vs baseline: 1.0589x; 1.0589x over previous
#include <cuda_runtime.h>
#include <cuda_fp16.h>
#include <cstdint>

#define NR 8192
#define DD 256

// ---------------- device scratch (allocation-free) ----------------
__device__ __align__(256) __half g_Xhi[NR * DD], g_Xlo[NR * DD];
__device__ __align__(256) __half g_XThi[DD * NR];
__device__ __align__(256) __half g_Whi[512 * DD], g_Wlo[512 * DD];     // [Rt/16 ; Et]
__device__ __align__(256) __half g_QKhi[NR * 512], g_QKlo[NR * 512];   // Q cols 0-255, K cols 256-511
__device__ __align__(256) float  g_L[(size_t)NR * NR];
__device__ __align__(256) __half g_Phi[(size_t)NR * NR];
__device__ __align__(256) float  g_Opart[2 * NR * DD];                 // split-K partials (16 MB)

// ---------------- PTX helpers ----------------
__device__ __forceinline__ uint32_t s2u(const void* p) {
    uint32_t a;
    asm("{ .reg .u64 t; cvta.to.shared.u64 t, %1; cvt.u32.u64 %0, t; }" : "=r"(a) : "l"(p));
    return a;
}
__device__ __forceinline__ void cpasync16(uint32_t dst, const void* src) {
    asm volatile("cp.async.cg.shared.global [%0], [%1], 16;" :: "r"(dst), "l"(src));
}
__device__ __forceinline__ void cp_commit() {
    asm volatile("cp.async.commit_group;" ::: "memory");
}
template <int N>
__device__ __forceinline__ void cp_wait() {
    asm volatile("cp.async.wait_group %0;" :: "n"(N) : "memory");
}
__device__ __forceinline__ void ldsm4(uint32_t* r, uint32_t a) {
    asm volatile("ldmatrix.sync.aligned.m8n8.x4.shared.b16 {%0,%1,%2,%3}, [%4];"
                 : "=r"(r[0]), "=r"(r[1]), "=r"(r[2]), "=r"(r[3]) : "r"(a));
}
__device__ __forceinline__ void mma16816(float* d, const uint32_t* a, const uint32_t* b) {
    asm volatile(
        "mma.sync.aligned.m16n8k16.row.col.f32.f16.f16.f32 "
        "{%0,%1,%2,%3}, {%4,%5,%6,%7}, {%8,%9}, {%0,%1,%2,%3};"
        : "+f"(d[0]), "+f"(d[1]), "+f"(d[2]), "+f"(d[3])
        : "r"(a[0]), "r"(a[1]), "r"(a[2]), "r"(a[3]), "r"(b[0]), "r"(b[1]));
}

// ---------------- prep: fp16 hi/lo splits ----------------
__global__ void __launch_bounds__(256) prep_params(const float* __restrict__ R,
                                                   const float* __restrict__ E) {
    int idx = blockIdx.x * 256 + threadIdx.x;   // 65536
    int k = idx >> 8, j = idx & 255;            // R[k][j]
    float r = R[idx] * 0.0625f;                 // fold 1/sqrt(d)=1/16 into rotation
    __half h = __float2half_rn(r);
    g_Whi[j * DD + k] = h;
    g_Wlo[j * DD + k] = __float2half_rn(r - __half2float(h));
    float e = E[idx];
    h = __float2half_rn(e);
    g_Whi[(256 + j) * DD + k] = h;
    g_Wlo[(256 + j) * DD + k] = __float2half_rn(e - __half2float(h));
}

__global__ void __launch_bounds__(256) prep_x(const float* __restrict__ X) {
    int idx = blockIdx.x * 256 + threadIdx.x;   // 2M
    int r = idx >> 8, c = idx & 255;
    float v = X[idx];
    __half h = __float2half_rn(v);
    g_Xhi[idx] = h;
    g_Xlo[idx] = __float2half_rn(v - __half2float(h));
    g_XThi[(size_t)c * NR + r] = h;
}

// =====================================================================
// Persistent wide 3-product GEMM: C = A @ B^T, CTA tile 128x256,
// 256 threads = 8 warps as 2m x 4n, each warp 64x64. BK=64,
// continuous 2-stage ring. (R9 interleaved MMA schedule.)
// mode 0: split fp16 out (Chi/Clo). mode 1: fp32 out (Cf).
// =====================================================================
#define STG512 98304

__device__ __forceinline__ void load512(char* st,
    const __half* pAh, const __half* pAl, int lda,
    const __half* pBh, const __half* pBl, int ldb, int kc, int tid) {
    const uint32_t b0 = s2u(st);
    #pragma unroll
    for (int i = 0; i < 4; ++i) {             // A tiles: 128x64
        int id = tid + i * 256;
        int r = id >> 3, q = id & 7;
        uint32_t off = (uint32_t)(r * 128) + (uint32_t)((q ^ (r & 7)) << 4);
        const size_t g = (size_t)r * lda + kc + q * 8;
        cpasync16(b0 + off, pAh + g);
        cpasync16(b0 + 16384 + off, pAl + g);
    }
    #pragma unroll
    for (int i = 0; i < 8; ++i) {             // B tiles: 256x64
        int id = tid + i * 256;
        int r = id >> 3, q = id & 7;
        uint32_t off = (uint32_t)(r * 128) + (uint32_t)((q ^ (r & 7)) << 4);
        const size_t g = (size_t)r * ldb + kc + q * 8;
        cpasync16(b0 + 32768 + off, pBh + g);
        cpasync16(b0 + 65536 + off, pBl + g);
    }
}

__device__ __forceinline__ void compute512(char* st, float acc[4][8][4],
                                           int lane, int wm, int wn) {
    const uint32_t bA = s2u(st), bAl = bA + 16384, bB = bA + 32768, bBl = bA + 65536;
    #pragma unroll
    for (int k16 = 0; k16 < 4; ++k16) {
        uint32_t ah[4][4], al[4][4];
        #pragma unroll
        for (int mt = 0; mt < 4; ++mt) {
            int row = wm * 64 + mt * 16 + (lane & 15);
            int c = k16 * 2 + (lane >> 4);
            uint32_t off = (uint32_t)(row * 128) + (uint32_t)((c ^ (row & 7)) << 4);
            ldsm4(ah[mt], bA + off);
            ldsm4(al[mt], bAl + off);
        }
        #pragma unroll
        for (int p = 0; p < 4; ++p) {
            int n = wn * 64 + p * 16 + ((lane >> 4) << 3) + (lane & 7);
            int c = k16 * 2 + ((lane >> 3) & 1);
            uint32_t off = (uint32_t)(n * 128) + (uint32_t)((c ^ (n & 7)) << 4);
            uint32_t bh[4], bl[4];
            ldsm4(bh, bB + off);
            ldsm4(bl, bBl + off);
            #pragma unroll
            for (int mt = 0; mt < 4; ++mt) {
                mma16816(acc[mt][2 * p + 0], ah[mt], &bh[0]);
                mma16816(acc[mt][2 * p + 1], ah[mt], &bh[2]);
                mma16816(acc[mt][2 * p + 0], al[mt], &bh[0]);
                mma16816(acc[mt][2 * p + 1], al[mt], &bh[2]);
                mma16816(acc[mt][2 * p + 0], ah[mt], &bl[0]);
                mma16816(acc[mt][2 * p + 1], ah[mt], &bl[2]);
            }
        }
    }
}

__device__ __forceinline__ void tile_ptrs512(int t, int bxm, int bxs,
    const __half* Ahi, const __half* Alo, const __half* Bhi, const __half* Blo,
    int lda, int ldb,
    const __half*& pAh, const __half*& pAl, const __half*& pBh, const __half*& pBl) {
    int by = t >> bxs, bx = t & bxm;
    pAh = Ahi + (size_t)(by * 128) * lda;
    pAl = Alo + (size_t)(by * 128) * lda;
    pBh = Bhi + (size_t)(bx * 256) * ldb;
    pBl = Blo + (size_t)(bx * 256) * ldb;
}

__global__ void __launch_bounds__(256, 1) gemm512p(
    const __half* __restrict__ Ahi, const __half* __restrict__ Alo, int lda,
    const __half* __restrict__ Bhi, const __half* __restrict__ Blo, int ldb,
    int K, int NT, int bxm, int bxs, int mode, float* __restrict__ Cf,
    __half* __restrict__ Chi, __half* __restrict__ Clo, int ldc) {
    extern __shared__ char sm[];
    const int tid = threadIdx.x, lane = tid & 31, wid = tid >> 5;
    const int wm = wid >> 2, wn = wid & 3;
    const int NC = K >> 6;

    int lt = blockIdx.x, lc = 0, ldbuf = 0;
    const __half *lAh, *lAl, *lBh, *lBl;
    tile_ptrs512(lt, bxm, bxs, Ahi, Alo, Bhi, Blo, lda, ldb, lAh, lAl, lBh, lBl);

    #pragma unroll
    for (int i = 0; i < 2; ++i) {
        if (lt < NT) {
            load512(sm + ldbuf * STG512, lAh, lAl, lda, lBh, lBl, ldb, lc * 64, tid);
            ldbuf ^= 1;
            if (++lc == NC) {
                lc = 0; lt += gridDim.x;
                if (lt < NT) tile_ptrs512(lt, bxm, bxs, Ahi, Alo, Bhi, Blo, lda, ldb, lAh, lAl, lBh, lBl);
            }
        }
        cp_commit();
    }

    int cbuf = 0;
    for (int t = blockIdx.x; t < NT; t += gridDim.x) {
        float acc[4][8][4];
        #pragma unroll
        for (int a = 0; a < 4; ++a)
            #pragma unroll
            for (int b = 0; b < 8; ++b)
                #pragma unroll
                for (int c = 0; c < 4; ++c) acc[a][b][c] = 0.f;

        for (int c = 0; c < NC; ++c) {
            cp_wait<1>();
            __syncthreads();
            compute512(sm + cbuf * STG512, acc, lane, wm, wn);
            cbuf ^= 1;
            __syncthreads();
            if (lt < NT) {
                load512(sm + ldbuf * STG512, lAh, lAl, lda, lBh, lBl, ldb, lc * 64, tid);
                ldbuf ^= 1;
                if (++lc == NC) {
                    lc = 0; lt += gridDim.x;
                    if (lt < NT) tile_ptrs512(lt, bxm, bxs, Ahi, Alo, Bhi, Blo, lda, ldb, lAh, lAl, lBh, lBl);
                }
            }
            cp_commit();
        }

        const int rowT = (t >> bxs) * 128, colT = (t & bxm) * 256;
        const int quad = lane >> 2, tc = lane & 3;
        #pragma unroll
        for (int mt = 0; mt < 4; ++mt) {
            #pragma unroll
            for (int h = 0; h < 2; ++h) {
                const int row = rowT + wm * 64 + mt * 16 + quad + h * 8;
                #pragma unroll
                for (int nt = 0; nt < 8; ++nt) {
                    const int col = colT + wn * 64 + nt * 8 + tc * 2;
                    float v0 = acc[mt][nt][h * 2 + 0];
                    float v1 = acc[mt][nt][h * 2 + 1];
                    if (mode == 1) {
                        *(float2*)(Cf + (size_t)row * ldc + col) = make_float2(v0, v1);
                    } else {
                        __half h0 = __float2half_rn(v0), h1 = __float2half_rn(v1);
                        __half l0 = __float2half_rn(v0 - __half2float(h0));
                        __half l1 = __float2half_rn(v1 - __half2float(h1));
                        *(__half2*)(Chi + (size_t)row * ldc + col) = __halves2half2(h0, h1);
                        *(__half2*)(Clo + (size_t)row * ldc + col) = __halves2half2(l0, l1);
                    }
                }
            }
        }
    }
}

// ---------------- row softmax: Phi = fp16(softmax(L)), shuffle reductions ----------------
__global__ void __launch_bounds__(256) softmax_k() {
    __shared__ float warpred[8];
    __shared__ float bc;
    const int row = blockIdx.x;
    const int t = threadIdx.x, lane = t & 31, w = t >> 5;
    const float4* Lr = (const float4*)(g_L + (size_t)row * NR);
    float4 v[8];
    float m = -3.4e38f;
    #pragma unroll
    for (int i = 0; i < 8; ++i) {
        v[i] = Lr[t + i * 256];
        m = fmaxf(m, fmaxf(fmaxf(v[i].x, v[i].y), fmaxf(v[i].z, v[i].w)));
    }
    #pragma unroll
    for (int o = 16; o > 0; o >>= 1) m = fmaxf(m, __shfl_xor_sync(0xFFFFFFFFu, m, o));
    if (lane == 0) warpred[w] = m;
    __syncthreads();
    if (w == 0) {
        float x = (lane < 8) ? warpred[lane] : -3.4e38f;
        #pragma unroll
        for (int o = 4; o > 0; o >>= 1) x = fmaxf(x, __shfl_xor_sync(0xFFFFFFFFu, x, o));
        if (lane == 0) bc = x;
    }
    __syncthreads();
    m = bc;
    float sum = 0.f;
    #pragma unroll
    for (int i = 0; i < 8; ++i) {
        v[i].x = __expf(v[i].x - m); v[i].y = __expf(v[i].y - m);
        v[i].z = __expf(v[i].z - m); v[i].w = __expf(v[i].w - m);
        sum += (v[i].x + v[i].y) + (v[i].z + v[i].w);
    }
    #pragma unroll
    for (int o = 16; o > 0; o >>= 1) sum += __shfl_xor_sync(0xFFFFFFFFu, sum, o);
    if (lane == 0) warpred[w] = sum;
    __syncthreads();
    if (w == 0) {
        float x = (lane < 8) ? warpred[lane] : 0.f;
        #pragma unroll
        for (int o = 4; o > 0; o >>= 1) x += __shfl_xor_sync(0xFFFFFFFFu, x, o);
        if (lane == 0) bc = x;
    }
    __syncthreads();
    const float inv = 1.0f / bc;
    uint2* ph = (uint2*)(g_Phi + (size_t)row * NR);
    #pragma unroll
    for (int i = 0; i < 8; ++i) {
        __half2 a = __floats2half2_rn(v[i].x * inv, v[i].y * inv);
        __half2 b = __floats2half2_rn(v[i].z * inv, v[i].w * inv);
        uint2 wv;
        wv.x = *(uint32_t*)&a;
        wv.y = *(uint32_t*)&b;
        ph[t + i * 256] = wv;
    }
}

// =====================================================================
// O split-K: Opart[half] = P[:, half] @ X^T[half]
// Grid (2, 64): x = KV half, y = row tile. CTA tile 128 rows x 256 cols
// (P read ONCE from HBM). 256 thr = 8 warps 2m x 4n, warp 64x64.
// BK=64 over 4096-deep KV half, 4-stage 48KB ring (192 KB smem).
// =====================================================================
#define OSTG 49152
#define ONST 4

__device__ __forceinline__ void load_os(char* st, const __half* pA, const __half* pB,
                                        int kc, int tid) {
    const uint32_t b0 = s2u(st);
    #pragma unroll
    for (int i = 0; i < 4; ++i) {             // A (P): 128x64
        int id = tid + i * 256;
        int r = id >> 3, q = id & 7;
        uint32_t off = (uint32_t)(r * 128) + (uint32_t)((q ^ (r & 7)) << 4);
        cpasync16(b0 + off, pA + (size_t)r * NR + kc + q * 8);
    }
    #pragma unroll
    for (int i = 0; i < 8; ++i) {             // B (X^T): 256x64
        int id = tid + i * 256;
        int r = id >> 3, q = id & 7;
        uint32_t off = (uint32_t)(r * 128) + (uint32_t)((q ^ (r & 7)) << 4);
        cpasync16(b0 + 16384 + off, pB + (size_t)r * NR + kc + q * 8);
    }
}

__global__ void __launch_bounds__(256, 1) gemm_os(float* __restrict__ Opart) {
    extern __shared__ char sm[];
    const int tid = threadIdx.x, lane = tid & 31, wid = tid >> 5;
    const int wm = wid >> 2, wn = wid & 3;
    const int half = blockIdx.x;
    const int rowA = blockIdx.y * 128;
    const int kvBase = half * (NR / 2);
    const __half* pA = g_Phi + (size_t)rowA * NR + kvBase;
    const __half* pB = g_XThi + kvBase;
    const int NCH = (NR / 2) >> 6;   // 64

    float acc[4][8][4];
    #pragma unroll
    for (int a = 0; a < 4; ++a)
        #pragma unroll
        for (int b = 0; b < 8; ++b)
            #pragma unroll
            for (int c = 0; c < 4; ++c) acc[a][b][c] = 0.f;

    #pragma unroll
    for (int s = 0; s < ONST; ++s) {
        if (s < NCH) load_os(sm + s * OSTG, pA, pB, s * 64, tid);
        cp_commit();
    }

    for (int c = 0; c < NCH; ++c) {
        cp_wait<ONST - 1>();
        __syncthreads();
        char* st = sm + (c % ONST) * OSTG;
        const uint32_t bA = s2u(st), bB = bA + 16384;
        #pragma unroll
        for (int k16 = 0; k16 < 4; ++k16) {
            uint32_t ah[4][4];
            #pragma unroll
            for (int mt = 0; mt < 4; ++mt) {
                int row = wm * 64 + mt * 16 + (lane & 15);
                int cc = k16 * 2 + (lane >> 4);
                uint32_t off = (uint32_t)(row * 128) + (uint32_t)((cc ^ (row & 7)) << 4);
                ldsm4(ah[mt], bA + off);
            }
            #pragma unroll
            for (int p = 0; p < 4; ++p) {
                int n = wn * 64 + p * 16 + ((lane >> 4) << 3) + (lane & 7);
                int cc = k16 * 2 + ((lane >> 3) & 1);
                uint32_t off = (uint32_t)(n * 128) + (uint32_t)((cc ^ (n & 7)) << 4);
                uint32_t bh[4];
                ldsm4(bh, bB + off);
                #pragma unroll
                for (int mt = 0; mt < 4; ++mt) {
                    mma16816(acc[mt][2 * p + 0], ah[mt], &bh[0]);
                    mma16816(acc[mt][2 * p + 1], ah[mt], &bh[2]);
                }
            }
        }
        __syncthreads();
        int nx = c + ONST;
        if (nx < NCH) load_os(sm + (nx % ONST) * OSTG, pA, pB, nx * 64, tid);
        cp_commit();
    }

    float* Co = Opart + (size_t)half * NR * DD;
    const int quad = lane >> 2, tc = lane & 3;
    #pragma unroll
    for (int mt = 0; mt < 4; ++mt)
        #pragma unroll
        for (int h = 0; h < 2; ++h) {
            const int row = rowA + wm * 64 + mt * 16 + quad + h * 8;
            #pragma unroll
            for (int nt = 0; nt < 8; ++nt) {
                const int col = wn * 64 + nt * 8 + tc * 2;
                *(float2*)(Co + (size_t)row * DD + col) =
                    make_float2(acc[mt][nt][h * 2 + 0], acc[mt][nt][h * 2 + 1]);
            }
        }
}

// ---------------- combine split-K partials ----------------
__global__ void __launch_bounds__(256) combine_o(float* __restrict__ out) {
    int i = blockIdx.x * 256 + threadIdx.x;   // float4 index; 524288 total
    const float4* p0 = (const float4*)g_Opart;
    const float4* p1 = (const float4*)(g_Opart + (size_t)NR * DD);
    float4 a = p0[i], b = p1[i];
    ((float4*)out)[i] = make_float4(a.x + b.x, a.y + b.y, a.z + b.z, a.w + b.w);
}

// ---------------- launch ----------------
extern "C" void kernel_launch(void* const* d_in, const int* in_sizes, int n_in,
                              void* d_out, int out_size) {
    const float* R = (const float*)d_in[0];
    const float* E = (const float*)d_in[1];
    const float* X = (const float*)d_in[2];
    float* out = (float*)d_out;

    const int SMEMW = 2 * STG512;        // 192 KB
    const int SMEMO = ONST * OSTG;       // 192 KB
    cudaFuncSetAttribute(gemm512p, cudaFuncAttributeMaxDynamicSharedMemorySize, SMEMW);
    cudaFuncSetAttribute(gemm_os, cudaFuncAttributeMaxDynamicSharedMemorySize, SMEMO);

    void *xhi, *xlo, *whi, *wlo, *qkhi, *qklo, *opart;
    cudaGetSymbolAddress(&xhi, g_Xhi);   cudaGetSymbolAddress(&xlo, g_Xlo);
    cudaGetSymbolAddress(&whi, g_Whi);   cudaGetSymbolAddress(&wlo, g_Wlo);
    cudaGetSymbolAddress(&qkhi, g_QKhi); cudaGetSymbolAddress(&qklo, g_QKlo);
    cudaGetSymbolAddress(&opart, g_Opart);
    void* lptr;
    cudaGetSymbolAddress(&lptr, g_L);

    prep_params<<<DD * DD / 256, 256>>>(R, E);
    prep_x<<<NR, 256>>>(X);

    // QK = X @ [R/16 | E]  (split out, ldc=512); 128 tiles (2 x 64)
    gemm512p<<<128, 256, SMEMW>>>((__half*)xhi, (__half*)xlo, DD,
                                  (__half*)whi, (__half*)wlo, DD,
                                  DD, 128, 1, 1, 0, nullptr,
                                  (__half*)qkhi, (__half*)qklo, 512);
    // L = Q @ K^T  (fp32 out); 2048 tiles (32 x 64), persistent 148 CTAs
    gemm512p<<<148, 256, SMEMW>>>((__half*)qkhi, (__half*)qklo, 512,
                                  (__half*)qkhi + 256, (__half*)qklo + 256, 512,
                                  DD, 2048, 31, 5, 1, (float*)lptr,
                                  nullptr, nullptr, NR);
    // P = softmax(L)
    softmax_k<<<NR, 256>>>();
    // O partials: split-K over KV halves, P read once
    gemm_os<<<dim3(2, 64), 256, SMEMO>>>((float*)opart);
    // combine partials -> out
    combine_o<<<(NR * DD / 4) / 256, 256>>>(out);
}

// round 15
// speedup vs baseline: 1.1252x; 1.0626x over previous
#include <cuda_runtime.h>
#include <cuda_fp16.h>
#include <cstdint>

#define NR 8192
#define DD 256

// ---------------- device scratch (allocation-free) ----------------
__device__ __align__(256) __half g_Xhi[NR * DD], g_Xlo[NR * DD];
__device__ __align__(256) __half g_XThi[DD * NR];
__device__ __align__(256) __half g_Whi[512 * DD], g_Wlo[512 * DD];     // [Rt/16 ; Et]
__device__ __align__(256) __half g_QKhi[NR * 512], g_QKlo[NR * 512];   // Q cols 0-255, K cols 256-511
__device__ __align__(256) float  g_L[(size_t)NR * NR];
__device__ __align__(256) __half g_Phi[(size_t)NR * NR];
__device__ __align__(256) float  g_Opart[2 * NR * DD];                 // split-K partials (16 MB)

// ---------------- PTX helpers ----------------
__device__ __forceinline__ uint32_t s2u(const void* p) {
    uint32_t a;
    asm("{ .reg .u64 t; cvta.to.shared.u64 t, %1; cvt.u32.u64 %0, t; }" : "=r"(a) : "l"(p));
    return a;
}
__device__ __forceinline__ void cpasync16(uint32_t dst, const void* src) {
    asm volatile("cp.async.cg.shared.global [%0], [%1], 16;" :: "r"(dst), "l"(src));
}
__device__ __forceinline__ void cp_commit() {
    asm volatile("cp.async.commit_group;" ::: "memory");
}
template <int N>
__device__ __forceinline__ void cp_wait() {
    asm volatile("cp.async.wait_group %0;" :: "n"(N) : "memory");
}
__device__ __forceinline__ void ldsm4(uint32_t* r, uint32_t a) {
    asm volatile("ldmatrix.sync.aligned.m8n8.x4.shared.b16 {%0,%1,%2,%3}, [%4];"
                 : "=r"(r[0]), "=r"(r[1]), "=r"(r[2]), "=r"(r[3]) : "r"(a));
}
__device__ __forceinline__ void mma16816(float* d, const uint32_t* a, const uint32_t* b) {
    asm volatile(
        "mma.sync.aligned.m16n8k16.row.col.f32.f16.f16.f32 "
        "{%0,%1,%2,%3}, {%4,%5,%6,%7}, {%8,%9}, {%0,%1,%2,%3};"
        : "+f"(d[0]), "+f"(d[1]), "+f"(d[2]), "+f"(d[3])
        : "r"(a[0]), "r"(a[1]), "r"(a[2]), "r"(a[3]), "r"(b[0]), "r"(b[1]));
}

// ---------------- prep: fp16 hi/lo splits ----------------
__global__ void __launch_bounds__(256) prep_params(const float* __restrict__ R,
                                                   const float* __restrict__ E) {
    int idx = blockIdx.x * 256 + threadIdx.x;   // 65536
    int k = idx >> 8, j = idx & 255;            // R[k][j]
    float r = R[idx] * 0.0625f;                 // fold 1/sqrt(d)=1/16 into rotation
    __half h = __float2half_rn(r);
    g_Whi[j * DD + k] = h;
    g_Wlo[j * DD + k] = __float2half_rn(r - __half2float(h));
    float e = E[idx];
    h = __float2half_rn(e);
    g_Whi[(256 + j) * DD + k] = h;
    g_Wlo[(256 + j) * DD + k] = __float2half_rn(e - __half2float(h));
}

// prep_x with smem transpose: coalesced XThi writes. Block = 64 rows.
__global__ void __launch_bounds__(256) prep_x(const float* __restrict__ X) {
    __shared__ __half st[256 * 66];    // [c][r], stride 66 to avoid bank conflicts
    const int t = threadIdx.x;
    const int rowbase = blockIdx.x * 64;
    #pragma unroll
    for (int i = 0; i < 16; ++i) {
        int id = t + i * 256;          // 4096 float4 per block
        int r = id >> 6, c4 = (id & 63) * 4;
        float4 v = *(const float4*)(X + (size_t)(rowbase + r) * 256 + c4);
        __half h0 = __float2half_rn(v.x), h1 = __float2half_rn(v.y);
        __half h2 = __float2half_rn(v.z), h3 = __float2half_rn(v.w);
        __half l0 = __float2half_rn(v.x - __half2float(h0));
        __half l1 = __float2half_rn(v.y - __half2float(h1));
        __half l2 = __float2half_rn(v.z - __half2float(h2));
        __half l3 = __float2half_rn(v.w - __half2float(h3));
        __half2 hh0 = __halves2half2(h0, h1), hh1 = __halves2half2(h2, h3);
        __half2 ll0 = __halves2half2(l0, l1), ll1 = __halves2half2(l2, l3);
        uint2 wh, wl;
        wh.x = *(uint32_t*)&hh0; wh.y = *(uint32_t*)&hh1;
        wl.x = *(uint32_t*)&ll0; wl.y = *(uint32_t*)&ll1;
        *(uint2*)(g_Xhi + (size_t)(rowbase + r) * 256 + c4) = wh;
        *(uint2*)(g_Xlo + (size_t)(rowbase + r) * 256 + c4) = wl;
        st[(c4 + 0) * 66 + r] = h0;
        st[(c4 + 1) * 66 + r] = h1;
        st[(c4 + 2) * 66 + r] = h2;
        st[(c4 + 3) * 66 + r] = h3;
    }
    __syncthreads();
    #pragma unroll
    for (int pass = 0; pass < 8; ++pass) {
        int c = (t >> 3) + pass * 32;
        int l = (t & 7) * 8;
        uint32_t w[4];
        #pragma unroll
        for (int j = 0; j < 4; ++j)
            w[j] = *(uint32_t*)&st[c * 66 + l + j * 2];
        *(uint4*)(g_XThi + (size_t)c * NR + rowbase + l) =
            make_uint4(w[0], w[1], w[2], w[3]);
    }
}

// =====================================================================
// Persistent 3-product GEMM: C = A @ B^T, CTA tile 128x128,
// 128 threads = 4 warps 2m x 2n, warp 64x64 (1:6 ldsm:MMA intensity).
// BK=32, packed-pair smem rows (two 64B rows per swizzled 128B line),
// 3-stage ring -> ONE __syncthreads per chunk. 2 CTAs/SM.
// mode 0: split fp16 out (Chi/Clo). mode 1: fp32 out (Cf).
// =====================================================================
#define STG128 32768     // Ahi 8K | Alo 8K | Bhi 8K | Blo 8K
#define NSTG 3

__device__ __forceinline__ uint32_t swz32(int r, int q) {
    return (uint32_t)((r >> 1) * 128 + (r & 1) * 64 + ((q ^ ((r >> 1) & 3)) << 4));
}

__device__ __forceinline__ void load128(char* st,
    const __half* pAh, const __half* pAl, int lda,
    const __half* pBh, const __half* pBl, int ldb, int kc, int tid) {
    const uint32_t b0 = s2u(st);
    #pragma unroll
    for (int i = 0; i < 4; ++i) {           // each tile: 128 rows x 32 cols = 512 vec16
        int id = tid + i * 128;
        int r = id >> 2, q = id & 3;
        uint32_t off = swz32(r, q);
        const size_t ga = (size_t)r * lda + kc + q * 8;
        const size_t gb = (size_t)r * ldb + kc + q * 8;
        cpasync16(b0 + off, pAh + ga);
        cpasync16(b0 + 8192 + off, pAl + ga);
        cpasync16(b0 + 16384 + off, pBh + gb);
        cpasync16(b0 + 24576 + off, pBl + gb);
    }
}

__device__ __forceinline__ void compute128(char* st, float acc[4][8][4],
                                           int lane, int wm, int wn) {
    const uint32_t bA = s2u(st), bAl = bA + 8192, bB = bA + 16384, bBl = bA + 24576;
    #pragma unroll
    for (int k16 = 0; k16 < 2; ++k16) {
        uint32_t ah[4][4], al[4][4];
        #pragma unroll
        for (int mt = 0; mt < 4; ++mt) {
            int row = wm * 64 + mt * 16 + (lane & 15);
            int q = k16 * 2 + (lane >> 4);
            uint32_t off = swz32(row, q);
            ldsm4(ah[mt], bA + off);
            ldsm4(al[mt], bAl + off);
        }
        #pragma unroll
        for (int p = 0; p < 4; ++p) {
            int n = wn * 64 + p * 16 + ((lane >> 4) << 3) + (lane & 7);
            int q = k16 * 2 + ((lane >> 3) & 1);
            uint32_t off = swz32(n, q);
            uint32_t bh[4], bl[4];
            ldsm4(bh, bB + off);
            ldsm4(bl, bBl + off);
            #pragma unroll
            for (int mt = 0; mt < 4; ++mt) {
                mma16816(acc[mt][2 * p + 0], ah[mt], &bh[0]);
                mma16816(acc[mt][2 * p + 1], ah[mt], &bh[2]);
                mma16816(acc[mt][2 * p + 0], al[mt], &bh[0]);
                mma16816(acc[mt][2 * p + 1], al[mt], &bh[2]);
                mma16816(acc[mt][2 * p + 0], ah[mt], &bl[0]);
                mma16816(acc[mt][2 * p + 1], ah[mt], &bl[2]);
            }
        }
    }
}

__device__ __forceinline__ void tile_ptrs128(int t, int bxm, int bxs,
    const __half* Ahi, const __half* Alo, const __half* Bhi, const __half* Blo,
    int lda, int ldb,
    const __half*& pAh, const __half*& pAl, const __half*& pBh, const __half*& pBl) {
    int by = t >> bxs, bx = t & bxm;
    pAh = Ahi + (size_t)(by * 128) * lda;
    pAl = Alo + (size_t)(by * 128) * lda;
    pBh = Bhi + (size_t)(bx * 128) * ldb;
    pBl = Blo + (size_t)(bx * 128) * ldb;
}

__global__ void __launch_bounds__(128, 2) gemm128p(
    const __half* __restrict__ Ahi, const __half* __restrict__ Alo, int lda,
    const __half* __restrict__ Bhi, const __half* __restrict__ Blo, int ldb,
    int K, int NT, int bxm, int bxs, int mode, float* __restrict__ Cf,
    __half* __restrict__ Chi, __half* __restrict__ Clo, int ldc) {
    extern __shared__ char sm[];
    const int tid = threadIdx.x, lane = tid & 31, wid = tid >> 5;
    const int wm = wid >> 1, wn = wid & 1;
    const int NC = K >> 5;     // BK=32

    // load cursor (runs 2 chunks ahead of compute)
    int lt = blockIdx.x, lc = 0, ldbuf = 0;
    const __half *lAh, *lAl, *lBh, *lBl;
    tile_ptrs128(lt, bxm, bxs, Ahi, Alo, Bhi, Blo, lda, ldb, lAh, lAl, lBh, lBl);

    // prologue: 2 chunks (3-stage ring, CUTLASS ordering)
    #pragma unroll
    for (int i = 0; i < 2; ++i) {
        if (lt < NT) {
            load128(sm + ldbuf * STG128, lAh, lAl, lda, lBh, lBl, ldb, lc * 32, tid);
            ldbuf = (ldbuf + 1) % NSTG;
            if (++lc == NC) {
                lc = 0; lt += gridDim.x;
                if (lt < NT) tile_ptrs128(lt, bxm, bxs, Ahi, Alo, Bhi, Blo, lda, ldb, lAh, lAl, lBh, lBl);
            }
        }
        cp_commit();
    }

    int cbuf = 0;
    for (int t = blockIdx.x; t < NT; t += gridDim.x) {
        float acc[4][8][4];
        #pragma unroll
        for (int a = 0; a < 4; ++a)
            #pragma unroll
            for (int b = 0; b < 8; ++b)
                #pragma unroll
                for (int c = 0; c < 4; ++c) acc[a][b][c] = 0.f;

        for (int c = 0; c < NC; ++c) {
            cp_wait<1>();
            __syncthreads();   // chunk c landed; all warps done with buffer loaded next
            if (lt < NT) {
                load128(sm + ldbuf * STG128, lAh, lAl, lda, lBh, lBl, ldb, lc * 32, tid);
                ldbuf = (ldbuf + 1) % NSTG;
                if (++lc == NC) {
                    lc = 0; lt += gridDim.x;
                    if (lt < NT) tile_ptrs128(lt, bxm, bxs, Ahi, Alo, Bhi, Blo, lda, ldb, lAh, lAl, lBh, lBl);
                }
            }
            cp_commit();
            compute128(sm + cbuf * STG128, acc, lane, wm, wn);
            cbuf = (cbuf + 1) % NSTG;
        }

        // epilogue for tile t
        const int rowT = (t >> bxs) * 128, colT = (t & bxm) * 128;
        const int quad = lane >> 2, tc = lane & 3;
        #pragma unroll
        for (int mt = 0; mt < 4; ++mt) {
            #pragma unroll
            for (int h = 0; h < 2; ++h) {
                const int row = rowT + wm * 64 + mt * 16 + quad + h * 8;
                #pragma unroll
                for (int nt = 0; nt < 8; ++nt) {
                    const int col = colT + wn * 64 + nt * 8 + tc * 2;
                    float v0 = acc[mt][nt][h * 2 + 0];
                    float v1 = acc[mt][nt][h * 2 + 1];
                    if (mode == 1) {
                        *(float2*)(Cf + (size_t)row * ldc + col) = make_float2(v0, v1);
                    } else {
                        __half h0 = __float2half_rn(v0), h1 = __float2half_rn(v1);
                        __half l0 = __float2half_rn(v0 - __half2float(h0));
                        __half l1 = __float2half_rn(v1 - __half2float(h1));
                        *(__half2*)(Chi + (size_t)row * ldc + col) = __halves2half2(h0, h1);
                        *(__half2*)(Clo + (size_t)row * ldc + col) = __halves2half2(l0, l1);
                    }
                }
            }
        }
    }
}

// ---------------- row softmax: Phi = fp16(softmax(L)), shuffle reductions ----------------
__global__ void __launch_bounds__(256) softmax_k() {
    __shared__ float warpred[8];
    __shared__ float bc;
    const int row = blockIdx.x;
    const int t = threadIdx.x, lane = t & 31, w = t >> 5;
    const float4* Lr = (const float4*)(g_L + (size_t)row * NR);
    float4 v[8];
    float m = -3.4e38f;
    #pragma unroll
    for (int i = 0; i < 8; ++i) {
        v[i] = Lr[t + i * 256];
        m = fmaxf(m, fmaxf(fmaxf(v[i].x, v[i].y), fmaxf(v[i].z, v[i].w)));
    }
    #pragma unroll
    for (int o = 16; o > 0; o >>= 1) m = fmaxf(m, __shfl_xor_sync(0xFFFFFFFFu, m, o));
    if (lane == 0) warpred[w] = m;
    __syncthreads();
    if (w == 0) {
        float x = (lane < 8) ? warpred[lane] : -3.4e38f;
        #pragma unroll
        for (int o = 4; o > 0; o >>= 1) x = fmaxf(x, __shfl_xor_sync(0xFFFFFFFFu, x, o));
        if (lane == 0) bc = x;
    }
    __syncthreads();
    m = bc;
    float sum = 0.f;
    #pragma unroll
    for (int i = 0; i < 8; ++i) {
        v[i].x = __expf(v[i].x - m); v[i].y = __expf(v[i].y - m);
        v[i].z = __expf(v[i].z - m); v[i].w = __expf(v[i].w - m);
        sum += (v[i].x + v[i].y) + (v[i].z + v[i].w);
    }
    #pragma unroll
    for (int o = 16; o > 0; o >>= 1) sum += __shfl_xor_sync(0xFFFFFFFFu, sum, o);
    if (lane == 0) warpred[w] = sum;
    __syncthreads();
    if (w == 0) {
        float x = (lane < 8) ? warpred[lane] : 0.f;
        #pragma unroll
        for (int o = 4; o > 0; o >>= 1) x += __shfl_xor_sync(0xFFFFFFFFu, x, o);
        if (lane == 0) bc = x;
    }
    __syncthreads();
    const float inv = 1.0f / bc;
    uint2* ph = (uint2*)(g_Phi + (size_t)row * NR);
    #pragma unroll
    for (int i = 0; i < 8; ++i) {
        __half2 a = __floats2half2_rn(v[i].x * inv, v[i].y * inv);
        __half2 b = __floats2half2_rn(v[i].z * inv, v[i].w * inv);
        uint2 wv;
        wv.x = *(uint32_t*)&a;
        wv.y = *(uint32_t*)&b;
        ph[t + i * 256] = wv;
    }
}

// =====================================================================
// O split-K: Opart[half] = P[:, half] @ X^T[half]
// Grid (2, 64). CTA 128 rows x 256 cols (P read ONCE). 256 thr =
// 8 warps 2m x 4n, warp 64x64. BK=64 over 4096 KV, 4-stage 48KB ring.
// =====================================================================
#define OSTG 49152
#define ONST 4

__device__ __forceinline__ void load_os(char* st, const __half* pA, const __half* pB,
                                        int kc, int tid) {
    const uint32_t b0 = s2u(st);
    #pragma unroll
    for (int i = 0; i < 4; ++i) {             // A (P): 128x64
        int id = tid + i * 256;
        int r = id >> 3, q = id & 7;
        uint32_t off = (uint32_t)(r * 128) + (uint32_t)((q ^ (r & 7)) << 4);
        cpasync16(b0 + off, pA + (size_t)r * NR + kc + q * 8);
    }
    #pragma unroll
    for (int i = 0; i < 8; ++i) {             // B (X^T): 256x64
        int id = tid + i * 256;
        int r = id >> 3, q = id & 7;
        uint32_t off = (uint32_t)(r * 128) + (uint32_t)((q ^ (r & 7)) << 4);
        cpasync16(b0 + 16384 + off, pB + (size_t)r * NR + kc + q * 8);
    }
}

__global__ void __launch_bounds__(256, 1) gemm_os(float* __restrict__ Opart) {
    extern __shared__ char sm[];
    const int tid = threadIdx.x, lane = tid & 31, wid = tid >> 5;
    const int wm = wid >> 2, wn = wid & 3;
    const int half = blockIdx.x;
    const int rowA = blockIdx.y * 128;
    const int kvBase = half * (NR / 2);
    const __half* pA = g_Phi + (size_t)rowA * NR + kvBase;
    const __half* pB = g_XThi + kvBase;
    const int NCH = (NR / 2) >> 6;   // 64

    float acc[4][8][4];
    #pragma unroll
    for (int a = 0; a < 4; ++a)
        #pragma unroll
        for (int b = 0; b < 8; ++b)
            #pragma unroll
            for (int c = 0; c < 4; ++c) acc[a][b][c] = 0.f;

    #pragma unroll
    for (int s = 0; s < ONST; ++s) {
        if (s < NCH) load_os(sm + s * OSTG, pA, pB, s * 64, tid);
        cp_commit();
    }

    for (int c = 0; c < NCH; ++c) {
        cp_wait<ONST - 1>();
        __syncthreads();
        char* st = sm + (c % ONST) * OSTG;
        const uint32_t bA = s2u(st), bB = bA + 16384;
        #pragma unroll
        for (int k16 = 0; k16 < 4; ++k16) {
            uint32_t ah[4][4];
            #pragma unroll
            for (int mt = 0; mt < 4; ++mt) {
                int row = wm * 64 + mt * 16 + (lane & 15);
                int cc = k16 * 2 + (lane >> 4);
                uint32_t off = (uint32_t)(row * 128) + (uint32_t)((cc ^ (row & 7)) << 4);
                ldsm4(ah[mt], bA + off);
            }
            #pragma unroll
            for (int p = 0; p < 4; ++p) {
                int n = wn * 64 + p * 16 + ((lane >> 4) << 3) + (lane & 7);
                int cc = k16 * 2 + ((lane >> 3) & 1);
                uint32_t off = (uint32_t)(n * 128) + (uint32_t)((cc ^ (n & 7)) << 4);
                uint32_t bh[4];
                ldsm4(bh, bB + off);
                #pragma unroll
                for (int mt = 0; mt < 4; ++mt) {
                    mma16816(acc[mt][2 * p + 0], ah[mt], &bh[0]);
                    mma16816(acc[mt][2 * p + 1], ah[mt], &bh[2]);
                }
            }
        }
        __syncthreads();
        int nx = c + ONST;
        if (nx < NCH) load_os(sm + (nx % ONST) * OSTG, pA, pB, nx * 64, tid);
        cp_commit();
    }

    float* Co = Opart + (size_t)half * NR * DD;
    const int quad = lane >> 2, tc = lane & 3;
    #pragma unroll
    for (int mt = 0; mt < 4; ++mt)
        #pragma unroll
        for (int h = 0; h < 2; ++h) {
            const int row = rowA + wm * 64 + mt * 16 + quad + h * 8;
            #pragma unroll
            for (int nt = 0; nt < 8; ++nt) {
                const int col = wn * 64 + nt * 8 + tc * 2;
                *(float2*)(Co + (size_t)row * DD + col) =
                    make_float2(acc[mt][nt][h * 2 + 0], acc[mt][nt][h * 2 + 1]);
            }
        }
}

// ---------------- combine split-K partials ----------------
__global__ void __launch_bounds__(256) combine_o(float* __restrict__ out) {
    int i = blockIdx.x * 256 + threadIdx.x;   // float4 index; 524288 total
    const float4* p0 = (const float4*)g_Opart;
    const float4* p1 = (const float4*)(g_Opart + (size_t)NR * DD);
    float4 a = p0[i], b = p1[i];
    ((float4*)out)[i] = make_float4(a.x + b.x, a.y + b.y, a.z + b.z, a.w + b.w);
}

// ---------------- launch ----------------
extern "C" void kernel_launch(void* const* d_in, const int* in_sizes, int n_in,
                              void* d_out, int out_size) {
    const float* R = (const float*)d_in[0];
    const float* E = (const float*)d_in[1];
    const float* X = (const float*)d_in[2];
    float* out = (float*)d_out;

    const int SMEMG = NSTG * STG128;     // 96 KB
    const int SMEMO = ONST * OSTG;       // 192 KB
    cudaFuncSetAttribute(gemm128p, cudaFuncAttributeMaxDynamicSharedMemorySize, SMEMG);
    cudaFuncSetAttribute(gemm_os, cudaFuncAttributeMaxDynamicSharedMemorySize, SMEMO);

    void *xhi, *xlo, *whi, *wlo, *qkhi, *qklo, *opart, *lptr;
    cudaGetSymbolAddress(&xhi, g_Xhi);   cudaGetSymbolAddress(&xlo, g_Xlo);
    cudaGetSymbolAddress(&whi, g_Whi);   cudaGetSymbolAddress(&wlo, g_Wlo);
    cudaGetSymbolAddress(&qkhi, g_QKhi); cudaGetSymbolAddress(&qklo, g_QKlo);
    cudaGetSymbolAddress(&opart, g_Opart);
    cudaGetSymbolAddress(&lptr, g_L);

    prep_params<<<DD * DD / 256, 256>>>(R, E);
    prep_x<<<NR / 64, 256>>>(X);

    // QK = X @ [R/16 | E]  (split out, ldc=512); 256 tiles (4 x 64)
    gemm128p<<<256, 128, SMEMG>>>((__half*)xhi, (__half*)xlo, DD,
                                  (__half*)whi, (__half*)wlo, DD,
                                  DD, 256, 3, 2, 0, nullptr,
                                  (__half*)qkhi, (__half*)qklo, 512);
    // L = Q @ K^T  (fp32 out); 4096 tiles (64 x 64), persistent 296 CTAs (2/SM)
    gemm128p<<<296, 128, SMEMG>>>((__half*)qkhi, (__half*)qklo, 512,
                                  (__half*)qkhi + 256, (__half*)qklo + 256, 512,
                                  DD, 4096, 63, 6, 1, (float*)lptr,
                                  nullptr, nullptr, NR);
    // P = softmax(L)
    softmax_k<<<NR, 256>>>();
    // O partials: split-K over KV halves, P read once
    gemm_os<<<dim3(2, 64), 256, SMEMO>>>((float*)opart);
    // combine partials -> out
    combine_o<<<(NR * DD / 4) / 256, 256>>>(out);
}